// round 4
// baseline (speedup 1.0000x reference)
#include <cuda_runtime.h>
#include <math.h>
#include <stdint.h>

// Problem constants
#define BB 4
#define SS 1024
#define DD 1024
#define HH 16
#define HD 64
#define NEG_V 10000.0f

// Scratch (static device arrays; no allocation allowed)
__device__ float g_qkv[BB * SS * 3 * DD];     // [4096, 3072]
__device__ float g_am[BB * SS * DD];          // merged heads [4096, 1024]

// ---------------------------------------------------------------------------
// tf32 helpers
// ---------------------------------------------------------------------------
__device__ __forceinline__ uint32_t f2tf(float f) {
    uint32_t u;
    asm("cvt.rna.tf32.f32 %0, %1;" : "=r"(u) : "f"(f));
    return u;
}

__device__ __forceinline__ void mma8(float* c, const uint32_t* a, const uint32_t* b) {
    asm volatile(
        "mma.sync.aligned.m16n8k8.row.col.f32.tf32.tf32.f32 "
        "{%0,%1,%2,%3}, {%4,%5,%6,%7}, {%8,%9}, {%0,%1,%2,%3};\n"
        : "+f"(c[0]), "+f"(c[1]), "+f"(c[2]), "+f"(c[3])
        : "r"(a[0]), "r"(a[1]), "r"(a[2]), "r"(a[3]), "r"(b[0]), "r"(b[1]));
}

// Fragment-pack index helpers (m16n8k8):
//  A value (r in 0..15 within m16 tile, kk in 0..7 within k8):
//    lane = ((r&7)<<2) | (kk&3),  reg = (r>>3) | ((kk>>2)<<1)   -> 4 regs, LDS.128
//  B value (n col c in 0..7, kk in 0..7):
//    lane = (c<<2) | (kk&3),      reg = kk>>2                   -> 2 regs, LDS.64

// ---------------------------------------------------------------------------
// Generic tf32 GEMM: C[M,N] = A[M,K] @ B[K,N] + bias[N]
// BM=128, BN=128, BK=16, 256 threads (8 warps: 4 in M x 2 in N, warp 32x64)
// ---------------------------------------------------------------------------
__global__ __launch_bounds__(256) void gemm_tf32_bias(
    const float* __restrict__ A, const float* __restrict__ B,
    const float* __restrict__ bias, float* __restrict__ C,
    int K, int lda, int ldb, int ldc)
{
    __shared__ __align__(16) uint32_t Ap[2][8][32][4];   // [ksub][mi][lane][reg]
    __shared__ __align__(16) uint32_t Bp[2][16][32][2];  // [ksub][ni][lane][reg]

    const int tid = threadIdx.x;
    const int lane = tid & 31;
    const int warp = tid >> 5;
    const int wm = warp & 3, wn = warp >> 2;
    const int rowStart = blockIdx.y * 128;
    const int colStart = blockIdx.x * 128;

    float acc[2][8][4];
#pragma unroll
    for (int mi = 0; mi < 2; mi++)
#pragma unroll
        for (int ni = 0; ni < 8; ni++)
#pragma unroll
            for (int r = 0; r < 4; r++) acc[mi][ni][r] = 0.f;

    float4 aR[2], bR[2];

#define G_LOADG(kb) do {                                                          \
    _Pragma("unroll")                                                             \
    for (int i = 0; i < 2; i++) {                                                 \
        int lin = tid * 2 + i;                                                    \
        aR[i] = *reinterpret_cast<const float4*>(                                 \
            &A[(size_t)(rowStart + (lin >> 2)) * lda + (kb) + ((lin & 3) << 2)]); \
        bR[i] = *reinterpret_cast<const float4*>(                                 \
            &B[(size_t)((kb) + (lin >> 5)) * ldb + colStart + ((lin & 31) << 2)]);\
    } } while (0)

#define G_STORES() do {                                                           \
    _Pragma("unroll")                                                             \
    for (int i = 0; i < 2; i++) {                                                 \
        int lin = tid * 2 + i;                                                    \
        int m = lin >> 2; int k0l = (lin & 3) << 2; int mi = m >> 4; int r = m & 15; \
        float va[4] = {aR[i].x, aR[i].y, aR[i].z, aR[i].w};                       \
        _Pragma("unroll")                                                         \
        for (int j = 0; j < 4; j++) {                                             \
            int k = k0l + j; int kk = k & 7; int ks = k >> 3;                     \
            Ap[ks][mi][((r & 7) << 2) | (kk & 3)][(r >> 3) | ((kk >> 2) << 1)] = f2tf(va[j]); \
        }                                                                         \
        int kB = lin >> 5; int n0 = (lin & 31) << 2; int kkB = kB & 7; int ksB = kB >> 3; \
        float vb[4] = {bR[i].x, bR[i].y, bR[i].z, bR[i].w};                       \
        _Pragma("unroll")                                                         \
        for (int j = 0; j < 4; j++) {                                             \
            int n = n0 + j;                                                       \
            Bp[ksB][n >> 3][((n & 7) << 2) | (kkB & 3)][kkB >> 2] = f2tf(vb[j]);  \
        }                                                                         \
    } } while (0)

#define G_COMPUTE() do {                                                          \
    _Pragma("unroll")                                                             \
    for (int ks = 0; ks < 2; ks++) {                                              \
        uint32_t af[2][4]; uint32_t bf[8][2];                                     \
        _Pragma("unroll")                                                         \
        for (int mi = 0; mi < 2; mi++)                                            \
            *reinterpret_cast<uint4*>(af[mi]) =                                   \
                *reinterpret_cast<const uint4*>(Ap[ks][wm * 2 + mi][lane]);       \
        _Pragma("unroll")                                                         \
        for (int ni = 0; ni < 8; ni++)                                            \
            *reinterpret_cast<uint2*>(bf[ni]) =                                   \
                *reinterpret_cast<const uint2*>(Bp[ks][wn * 8 + ni][lane]);       \
        _Pragma("unroll")                                                         \
        for (int mi = 0; mi < 2; mi++)                                            \
            _Pragma("unroll")                                                     \
            for (int ni = 0; ni < 8; ni++)                                        \
                mma8(acc[mi][ni], af[mi], bf[ni]);                                \
    } } while (0)

    G_LOADG(0);
    G_STORES();
    __syncthreads();
    for (int kb = 16; kb < K; kb += 16) {
        G_LOADG(kb);
        G_COMPUTE();
        __syncthreads();
        G_STORES();
        __syncthreads();
    }
    G_COMPUTE();

    // epilogue
#pragma unroll
    for (int mi = 0; mi < 2; mi++)
#pragma unroll
        for (int ni = 0; ni < 8; ni++) {
            int row = rowStart + wm * 32 + mi * 16 + (lane >> 2);
            int col = colStart + wn * 64 + ni * 8 + (lane & 3) * 2;
            float b0 = bias[col], b1 = bias[col + 1];
            C[(size_t)row * ldc + col]           = acc[mi][ni][0] + b0;
            C[(size_t)row * ldc + col + 1]       = acc[mi][ni][1] + b1;
            C[(size_t)(row + 8) * ldc + col]     = acc[mi][ni][2] + b0;
            C[(size_t)(row + 8) * ldc + col + 1] = acc[mi][ni][3] + b1;
        }
}

// ---------------------------------------------------------------------------
// Fused attention middle: per block = 32 query rows of one (b,h).
//   Phase A: S = scale*Q@K^T + causal/mask  -> smem strip [32][1032]
//   Phase B: softmax rows in smem; write probs to w_out (only big DRAM write);
//            store tf32-converted probs back in place
//   Phase C: O = P@V via mma, A-fragments read straight from the strip
// 256 threads (8 warps). Dynamic smem ~173KB -> 1 CTA/SM.
// ---------------------------------------------------------------------------
#define SSTRIDE 1032   // 1024 + 8 floats: 8 mod 32 rotation kills LDS conflicts

struct FusedSmem {
    float scores[32][SSTRIDE];               // 132096 B
    uint32_t Ap[8][2][32][4];                // Q fragments, 8KB
    union {
        uint32_t Kp[8][16][32][2];           // K fragments (phase A), 32KB
        uint32_t Vp[16][8][32][2];           // V fragments (phase C), 32KB
    } kv;
};

__global__ __launch_bounds__(256) void attn_fused(
    const float* __restrict__ qkv, const float* __restrict__ mask,
    float* __restrict__ Wout, float* __restrict__ Am)
{
    extern __shared__ __align__(16) char smem_raw[];
    FusedSmem& sm = *reinterpret_cast<FusedSmem*>(smem_raw);

    const int tid = threadIdx.x;
    const int lane = tid & 31;
    const int warp = tid >> 5;
    const int qt = blockIdx.x;        // 0..31
    const int z = blockIdx.y;         // b*H + h
    const int b = z >> 4, h = z & 15;
    const int wm = warp & 1;          // m16 half (rows wm*16..wm*16+15)
    const int wn = warp >> 1;         // col group

    const float* Qb = qkv + (size_t)b * SS * 3 * DD + h * HD;
    const float* Kb = Qb + DD;
    const float* Vb = Qb + 2 * DD;
    const float* mrow = mask + (size_t)b * SS;

    // ---- pack Q tile (32 x 64) into fragments ----
#pragma unroll
    for (int i = 0; i < 2; i++) {
        int lin = tid * 2 + i;
        int m = lin >> 4, c4 = (lin & 15) << 2;
        float4 v = *reinterpret_cast<const float4*>(
            &Qb[(size_t)(qt * 32 + m) * (3 * DD) + c4]);
        float va[4] = {v.x, v.y, v.z, v.w};
        int mi = m >> 4, r = m & 15;
#pragma unroll
        for (int j = 0; j < 4; j++) {
            int k = c4 + j, kk = k & 7, ks = k >> 3;
            sm.Ap[ks][mi][((r & 7) << 2) | (kk & 3)][(r >> 3) | ((kk >> 2) << 1)] = f2tf(va[j]);
        }
    }

    // ---- Phase A: scores ----
    for (int kt = 0; kt < 8; kt++) {
        __syncthreads();   // Kp reuse / Ap ready
        // pack K tile: 128 (n) x 64 (k)
#pragma unroll
        for (int t = 0; t < 8; t++) {
            int lin = tid + t * 256;
            int n = lin >> 4, c4 = (lin & 15) << 2;
            float4 v = *reinterpret_cast<const float4*>(
                &Kb[(size_t)(kt * 128 + n) * (3 * DD) + c4]);
            float va[4] = {v.x, v.y, v.z, v.w};
#pragma unroll
            for (int j = 0; j < 4; j++) {
                int k = c4 + j, kk = k & 7, ks = k >> 3;
                sm.kv.Kp[ks][n >> 3][((n & 7) << 2) | (kk & 3)][kk >> 2] = f2tf(va[j]);
            }
        }
        __syncthreads();

        float acc[4][4];
#pragma unroll
        for (int nt = 0; nt < 4; nt++)
#pragma unroll
            for (int r = 0; r < 4; r++) acc[nt][r] = 0.f;

#pragma unroll
        for (int ks = 0; ks < 8; ks++) {
            uint32_t af[4];
            *reinterpret_cast<uint4*>(af) =
                *reinterpret_cast<const uint4*>(sm.Ap[ks][wm][lane]);
#pragma unroll
            for (int nt = 0; nt < 4; nt++) {
                uint32_t bf[2];
                *reinterpret_cast<uint2*>(bf) =
                    *reinterpret_cast<const uint2*>(sm.kv.Kp[ks][wn * 4 + nt][lane]);
                mma8(acc[nt], af, bf);
            }
        }

        // epilogue: scale + causal + mask -> scores smem
        int row0 = wm * 16 + (lane >> 2);
#pragma unroll
        for (int nt = 0; nt < 4; nt++) {
            int col = kt * 128 + (wn * 4 + nt) * 8 + (lane & 3) * 2;
            float m0 = mrow[col], m1 = mrow[col + 1];
#pragma unroll
            for (int half = 0; half < 2; half++) {
                int rl = row0 + half * 8;
                int qg = qt * 32 + rl;
                float v0 = (qg >= col)     ? acc[nt][half * 2 + 0] * 0.125f : -NEG_V;
                float v1 = (qg >= col + 1) ? acc[nt][half * 2 + 1] * 0.125f : -NEG_V;
                sm.scores[rl][col]     = v0 + m0;
                sm.scores[rl][col + 1] = v1 + m1;
            }
        }
    }
    __syncthreads();

    // ---- Phase B: softmax (warp handles rows warp*4 .. warp*4+3) ----
#pragma unroll
    for (int rr = 0; rr < 4; rr++) {
        int r = warp * 4 + rr;
        float4 v[8];
        float mx = -INFINITY;
#pragma unroll
        for (int c = 0; c < 8; c++) {
            v[c] = *reinterpret_cast<const float4*>(&sm.scores[r][lane * 4 + c * 128]);
            mx = fmaxf(mx, fmaxf(fmaxf(v[c].x, v[c].y), fmaxf(v[c].z, v[c].w)));
        }
#pragma unroll
        for (int o = 16; o > 0; o >>= 1) mx = fmaxf(mx, __shfl_xor_sync(0xffffffffu, mx, o));
        float s = 0.f;
#pragma unroll
        for (int c = 0; c < 8; c++) {
            v[c].x = __expf(v[c].x - mx);
            v[c].y = __expf(v[c].y - mx);
            v[c].z = __expf(v[c].z - mx);
            v[c].w = __expf(v[c].w - mx);
            s += (v[c].x + v[c].y) + (v[c].z + v[c].w);
        }
#pragma unroll
        for (int o = 16; o > 0; o >>= 1) s += __shfl_xor_sync(0xffffffffu, s, o);
        float inv = 1.0f / s;

        float* wrow = &Wout[((size_t)z * SS + qt * 32 + r) * SS];
        uint32_t* srow = reinterpret_cast<uint32_t*>(sm.scores[r]);
#pragma unroll
        for (int c = 0; c < 8; c++) {
            float4 p;
            p.x = v[c].x * inv; p.y = v[c].y * inv;
            p.z = v[c].z * inv; p.w = v[c].w * inv;
            *reinterpret_cast<float4*>(&wrow[lane * 4 + c * 128]) = p;
            uint4 t;
            t.x = f2tf(p.x); t.y = f2tf(p.y); t.z = f2tf(p.z); t.w = f2tf(p.w);
            *reinterpret_cast<uint4*>(&srow[lane * 4 + c * 128]) = t;
        }
    }

    // ---- Phase C: O = P @ V ----
    float oacc[2][4];
#pragma unroll
    for (int nt = 0; nt < 2; nt++)
#pragma unroll
        for (int r = 0; r < 4; r++) oacc[nt][r] = 0.f;

    const int r0 = wm * 16 + (lane >> 2);
    const uint32_t* s0 = reinterpret_cast<const uint32_t*>(sm.scores[r0]);
    const uint32_t* s1 = reinterpret_cast<const uint32_t*>(sm.scores[r0 + 8]);

    for (int kt = 0; kt < 8; kt++) {
        __syncthreads();   // scores tf32 ready (first iter) / Vp reuse
        // pack V tile: 128 (k) x 64 (n)
#pragma unroll
        for (int t = 0; t < 8; t++) {
            int lin = tid + t * 256;
            int k = lin >> 4, c4 = (lin & 15) << 2;
            float4 v = *reinterpret_cast<const float4*>(
                &Vb[(size_t)(kt * 128 + k) * (3 * DD) + c4]);
            float va[4] = {v.x, v.y, v.z, v.w};
            int kk = k & 7, ks = k >> 3;
#pragma unroll
            for (int j = 0; j < 4; j++) {
                int n = c4 + j;
                sm.kv.Vp[ks][n >> 3][((n & 7) << 2) | (kk & 3)][kk >> 2] = f2tf(va[j]);
            }
        }
        __syncthreads();

#pragma unroll
        for (int ks = 0; ks < 16; ks++) {
            int kbase = kt * 128 + ks * 8;
            uint32_t af[4];
            af[0] = s0[kbase + (lane & 3)];
            af[1] = s1[kbase + (lane & 3)];
            af[2] = s0[kbase + 4 + (lane & 3)];
            af[3] = s1[kbase + 4 + (lane & 3)];
#pragma unroll
            for (int nt = 0; nt < 2; nt++) {
                uint32_t bf[2];
                *reinterpret_cast<uint2*>(bf) =
                    *reinterpret_cast<const uint2*>(sm.kv.Vp[ks][wn * 2 + nt][lane]);
                mma8(oacc[nt], af, bf);
            }
        }
    }

    // epilogue: merged-head layout
#pragma unroll
    for (int nt = 0; nt < 2; nt++) {
        int col = h * HD + (wn * 2 + nt) * 8 + (lane & 3) * 2;
        float* o0 = &Am[((size_t)b * SS + qt * 32 + r0) * DD + col];
        float* o1 = &Am[((size_t)b * SS + qt * 32 + r0 + 8) * DD + col];
        o0[0] = oacc[nt][0]; o0[1] = oacc[nt][1];
        o1[0] = oacc[nt][2]; o1[1] = oacc[nt][3];
    }
}

// ---------------------------------------------------------------------------
extern "C" void kernel_launch(void* const* d_in, const int* in_sizes, int n_in,
                              void* d_out, int out_size)
{
    const float* x      = (const float*)d_in[0];   // [4,1024,1024]
    const float* mask   = (const float*)d_in[1];   // [4,1,1,1024]
    const float* w_attn = (const float*)d_in[2];   // [1024,3072]
    const float* b_attn = (const float*)d_in[3];   // [1,3072]
    const float* w_proj = (const float*)d_in[4];   // [1024,1024]
    const float* b_proj = (const float*)d_in[5];   // [1,1024]

    float* out = (float*)d_out;
    float* a_out = out;                                  // [4,1024,1024]
    float* w_out = out + (size_t)BB * SS * DD;           // [4,16,1024,1024]

    float* qkv = nullptr;
    float* am = nullptr;
    cudaGetSymbolAddress((void**)&qkv, g_qkv);
    cudaGetSymbolAddress((void**)&am, g_am);

    // allow ~173KB dynamic smem for the fused kernel (attribute set is
    // idempotent and capture-safe: it is not a stream operation)
    const int fused_smem = (int)sizeof(FusedSmem);
    cudaFuncSetAttribute(attn_fused,
                         cudaFuncAttributeMaxDynamicSharedMemorySize, fused_smem);

    // 1) qkv = x @ w_attn + b_attn   (4096 x 3072 x 1024)
    {
        dim3 grid(3 * DD / 128, BB * SS / 128);
        gemm_tf32_bias<<<grid, 256>>>(x, w_attn, b_attn, qkv,
                                      DD, DD, 3 * DD, 3 * DD);
    }
    // 2-4) fused: scores -> softmax -> probs out + O = P@V
    {
        dim3 grid(SS / 32, BB * HH);
        attn_fused<<<grid, 256, fused_smem>>>(qkv, mask, w_out, am);
    }
    // 5) a = a_merged @ w_proj + b_proj -> a_out
    {
        dim3 grid(DD / 128, BB * SS / 128);
        gemm_tf32_bias<<<grid, 256>>>(am, w_proj, b_proj, a_out,
                                      DD, DD, DD, DD);
    }
}